// round 1
// baseline (speedup 1.0000x reference)
#include <cuda_runtime.h>
#include <cstdint>

// Spatial RNN, 4 directions, R=8 chain steps, C=64 channels.
// x: (8,192,192,64) fp32; W_left/right/up/down: (64,64); out: (8,192,192,256)
// out[..., 0:64]=left, 64:128=right, 128:192=up, 192:256=down
//
// One CTA per scan line (1536 horizontal rows + 1536 vertical columns).
// Per line: 2 directions x 8 steps of [192,64]x[64,64] GEMM via mma.sync tf32,
// with relu + 1-pixel shift between steps (zero boundary = reference zero-pad).

#define LINE 192
#define CCH 64
#define RSTEPS 8
#define LSTR 68            // padded smem row stride (floats) -> conflict-free-ish
#define NLINES_H 1536      // 8*192
#define SMEM_BYTES ((2*LINE*LSTR + 2*CCH*LSTR) * 4)   // 139264

__device__ __forceinline__ float tf32r(float v) {
    float r;
    asm("cvt.rna.tf32.f32 %0, %1;" : "=f"(r) : "f"(v));
    return r;
}

__device__ __forceinline__ void mma_tf32(float c[4], const float a[4], const float b[2]) {
    const uint32_t* A = reinterpret_cast<const uint32_t*>(a);
    const uint32_t* B = reinterpret_cast<const uint32_t*>(b);
    asm volatile(
        "mma.sync.aligned.m16n8k8.row.col.f32.tf32.tf32.f32 "
        "{%0,%1,%2,%3}, {%4,%5,%6,%7}, {%8,%9}, {%0,%1,%2,%3};"
        : "+f"(c[0]), "+f"(c[1]), "+f"(c[2]), "+f"(c[3])
        : "r"(A[0]), "r"(A[1]), "r"(A[2]), "r"(A[3]), "r"(B[0]), "r"(B[1]));
}

extern "C" __global__ void __launch_bounds__(256, 1)
rnn_kernel(const float* __restrict__ x,
           const float* __restrict__ W_left, const float* __restrict__ W_right,
           const float* __restrict__ W_up,   const float* __restrict__ W_down,
           float* __restrict__ out)
{
    extern __shared__ float smem[];
    float* Xs = smem;                        // [192][68] raw fp32 line
    float* Ts = Xs + LINE * LSTR;            // [192][68] chain state (relu'd fp32)
    float* Wf = Ts + LINE * LSTR;            // [64][68]  forward W (tf32-rounded)
    float* Wb = Wf + CCH * LSTR;             // [64][68]  backward W (tf32-rounded)

    const int tid  = threadIdx.x;
    const int lane = tid & 31;
    const int warp = tid >> 5;
    const int mg   = warp & 3;               // 4 m-groups of 48 rows
    const int ng   = warp >> 2;              // 2 n-groups of 32 cols
    const int gID  = lane >> 2;              // 0..7
    const int tg   = lane & 3;               // 0..3

    long inBase, outBase;
    int pixIn, pixOut, chBase;
    const float *Wfp, *Wbp;
    {
        int l = blockIdx.x;
        if (l < NLINES_H) {
            // horizontal row: b = l/192, h = l%192
            inBase  = (long)l * (192 * 64);
            outBase = (long)l * (192 * 256);
            pixIn   = 64;
            pixOut  = 256;
            chBase  = 0;
            Wfp = W_left;  Wbp = W_right;
        } else {
            l -= NLINES_H;
            int b = l / 192, w = l % 192;
            inBase  = (long)b * (192 * 192 * 64)  + (long)w * 64;
            outBase = (long)b * (192 * 192 * 256) + (long)w * 256;
            pixIn   = 192 * 64;
            pixOut  = 192 * 256;
            chBase  = 128;
            Wfp = W_up;  Wbp = W_down;
        }
    }
    const float* xl = x + inBase;
    float* ol = out + outBase;

    // ---- load line into Xs (raw fp32), weights into Wf/Wb (tf32-rounded) ----
    for (int i = tid; i < LINE * 16; i += 256) {
        int p = i >> 4, q = (i & 15) << 2;
        float4 v = *reinterpret_cast<const float4*>(xl + (long)p * pixIn + q);
        *reinterpret_cast<float4*>(&Xs[p * LSTR + q]) = v;
    }
    for (int i = tid; i < CCH * 16; i += 256) {
        int p = i >> 4, q = (i & 15) << 2;
        float4 vf = *reinterpret_cast<const float4*>(Wfp + p * 64 + q);
        float4 vb = *reinterpret_cast<const float4*>(Wbp + p * 64 + q);
        vf.x = tf32r(vf.x); vf.y = tf32r(vf.y); vf.z = tf32r(vf.z); vf.w = tf32r(vf.w);
        vb.x = tf32r(vb.x); vb.y = tf32r(vb.y); vb.z = tf32r(vb.z); vb.w = tf32r(vb.w);
        *reinterpret_cast<float4*>(&Wf[p * LSTR + q]) = vf;
        *reinterpret_cast<float4*>(&Wb[p * LSTR + q]) = vb;
    }
    __syncthreads();

    const int m0 = mg * 48;
    const int n0 = ng * 32;

    #pragma unroll 1
    for (int dir = 0; dir < 2; dir++) {
        const float* Wsm = dir ? Wb : Wf;
        const int shift  = dir ? 1 : -1;   // fwd reads p-1, bwd reads p+1

        float acc[3][4][4];
        #pragma unroll
        for (int mt = 0; mt < 3; mt++)
            #pragma unroll
            for (int nt = 0; nt < 4; nt++)
                #pragma unroll
                for (int e = 0; e < 4; e++)
                    acc[mt][nt][e] = 0.f;

        const float* src = Xs;
        #pragma unroll 1
        for (int s = 0; s < RSTEPS; s++) {
            float Cf[3][4][4];
            #pragma unroll
            for (int mt = 0; mt < 3; mt++)
                #pragma unroll
                for (int nt = 0; nt < 4; nt++)
                    #pragma unroll
                    for (int e = 0; e < 4; e++)
                        Cf[mt][nt][e] = 0.f;

            #pragma unroll
            for (int kc = 0; kc < 8; kc++) {
                float a[3][4];
                #pragma unroll
                for (int mt = 0; mt < 3; mt++) {
                    int rA = m0 + mt * 16 + gID + shift;
                    int rB = rA + 8;
                    int c0 = kc * 8 + tg;
                    float a0 = ((unsigned)rA < (unsigned)LINE) ? src[rA * LSTR + c0]     : 0.f;
                    float a1 = ((unsigned)rB < (unsigned)LINE) ? src[rB * LSTR + c0]     : 0.f;
                    float a2 = ((unsigned)rA < (unsigned)LINE) ? src[rA * LSTR + c0 + 4] : 0.f;
                    float a3 = ((unsigned)rB < (unsigned)LINE) ? src[rB * LSTR + c0 + 4] : 0.f;
                    a[mt][0] = tf32r(a0); a[mt][1] = tf32r(a1);
                    a[mt][2] = tf32r(a2); a[mt][3] = tf32r(a3);
                }
                float b[4][2];
                #pragma unroll
                for (int nt = 0; nt < 4; nt++) {
                    int kk = kc * 8 + tg;
                    int nn = n0 + nt * 8 + gID;
                    b[nt][0] = Wsm[kk * LSTR + nn];
                    b[nt][1] = Wsm[(kk + 4) * LSTR + nn];
                }
                #pragma unroll
                for (int mt = 0; mt < 3; mt++)
                    #pragma unroll
                    for (int nt = 0; nt < 4; nt++)
                        mma_tf32(Cf[mt][nt], a[mt], b[nt]);
            }

            __syncthreads();   // all reads of src done before overwriting Ts

            #pragma unroll
            for (int mt = 0; mt < 3; mt++) {
                int r = m0 + mt * 16 + gID;
                #pragma unroll
                for (int nt = 0; nt < 4; nt++) {
                    int cc = n0 + nt * 8 + 2 * tg;
                    float v0 = fmaxf(Cf[mt][nt][0], 0.f);
                    float v1 = fmaxf(Cf[mt][nt][1], 0.f);
                    float v2 = fmaxf(Cf[mt][nt][2], 0.f);
                    float v3 = fmaxf(Cf[mt][nt][3], 0.f);
                    acc[mt][nt][0] += v0;  acc[mt][nt][1] += v1;
                    acc[mt][nt][2] += v2;  acc[mt][nt][3] += v3;
                    Ts[r * LSTR + cc]           = v0;
                    Ts[r * LSTR + cc + 1]       = v1;
                    Ts[(r + 8) * LSTR + cc]     = v2;
                    Ts[(r + 8) * LSTR + cc + 1] = v3;
                }
            }
            __syncthreads();
            src = Ts;
        }

        // ---- epilogue: out = x + acc ----
        const int cb = chBase + dir * 64;
        #pragma unroll
        for (int mt = 0; mt < 3; mt++) {
            int r = m0 + mt * 16 + gID;
            #pragma unroll
            for (int nt = 0; nt < 4; nt++) {
                int cc = n0 + nt * 8 + 2 * tg;
                float2 x0 = *reinterpret_cast<const float2*>(&Xs[r * LSTR + cc]);
                float2 x1 = *reinterpret_cast<const float2*>(&Xs[(r + 8) * LSTR + cc]);
                float2 o0 = make_float2(x0.x + acc[mt][nt][0], x0.y + acc[mt][nt][1]);
                float2 o1 = make_float2(x1.x + acc[mt][nt][2], x1.y + acc[mt][nt][3]);
                *reinterpret_cast<float2*>(ol + (long)r       * pixOut + cb + cc) = o0;
                *reinterpret_cast<float2*>(ol + (long)(r + 8) * pixOut + cb + cc) = o1;
            }
        }
    }
}

extern "C" void kernel_launch(void* const* d_in, const int* in_sizes, int n_in,
                              void* d_out, int out_size)
{
    const float* x  = (const float*)d_in[0];
    const float* wl = (const float*)d_in[1];
    const float* wr = (const float*)d_in[2];
    const float* wu = (const float*)d_in[3];
    const float* wd = (const float*)d_in[4];
    float* out = (float*)d_out;

    cudaFuncSetAttribute(rnn_kernel, cudaFuncAttributeMaxDynamicSharedMemorySize, SMEM_BYTES);
    rnn_kernel<<<3072, 256, SMEM_BYTES>>>(x, wl, wr, wu, wd, out);
}